// round 1
// baseline (speedup 1.0000x reference)
#include <cuda_runtime.h>
#include <math.h>

#define BB   16
#define TT   24
#define HH   96
#define WW   96
#define CIN  16
#define FF   16
#define GG   64   // 4*FF gate channels

// spatial tile
#define TLX  32
#define TLY  16
#define HCX  (TLX + 2)   // 34
#define HCY  (TLY + 2)   // 18
#define PLANE (HCY * HCX) // 612 floats per channel plane

#define STATE_ELEMS (BB * HH * WW * FF)

// scratch state (device globals: no allocation allowed in kernel_launch)
__device__ __align__(16) float g_h[2][STATE_ELEMS];
__device__ __align__(16) float g_c[STATE_ELEMS];

// smem layout (floats): [ swx: 9*16*64 ][ swh: 9*16*64 ][ sx: 16*PLANE ][ sh: 16*PLANE ]
#define SMEM_FLOATS (2 * 9 * CIN * GG + 2 * CIN * PLANE)
#define SMEM_BYTES  (SMEM_FLOATS * 4)   // 152064 B

__global__ void zero_state_kernel() {
    int n = STATE_ELEMS;
    for (int i = blockIdx.x * blockDim.x + threadIdx.x; i < n;
         i += gridDim.x * blockDim.x) {
        g_h[0][i] = 0.f;
        g_c[i]    = 0.f;
    }
}

__global__ __launch_bounds__(TLX * TLY, 1)
void lstm_step_kernel(const float* __restrict__ x,
                      const float* __restrict__ wx,
                      const float* __restrict__ wh,
                      const float* __restrict__ bias,
                      const float* __restrict__ h_in,
                      float* __restrict__ h_out,
                      float* __restrict__ c_state,
                      int t)
{
    extern __shared__ float smem[];
    float* swx = smem;                       // 9216
    float* swh = swx + 9 * CIN * GG;         // 9216
    float* sx  = swh + 9 * CIN * GG;         // 16*612
    float* sh  = sx  + CIN * PLANE;          // 16*612

    const int tx  = threadIdx.x;             // 0..31
    const int ty  = threadIdx.y;             // 0..15
    const int tid = ty * TLX + tx;           // 0..511
    const int bx  = blockIdx.x * TLX;
    const int by  = blockIdx.y * TLY;
    const int b   = blockIdx.z;

    // ---- stage weights to smem (vector copies) ----
    {
        const float4* wx4 = (const float4*)wx;
        const float4* wh4 = (const float4*)wh;
        float4* swx4 = (float4*)swx;
        float4* swh4 = (float4*)swh;
        #pragma unroll 1
        for (int i = tid; i < 9 * CIN * GG / 4; i += TLX * TLY) {
            swx4[i] = wx4[i];
            swh4[i] = wh4[i];
        }
    }

    // ---- stage x tile + halo and h tile + halo (channel-major planes) ----
    {
        const long xbase = ((long)(b * TT + t)) * (HH * WW * CIN);
        const long hbase = ((long)b) * (HH * WW * FF);
        #pragma unroll 1
        for (int i = tid; i < PLANE * 4; i += TLX * TLY) {
            int p   = i >> 2;           // pixel in halo tile
            int c4  = i & 3;            // which float4 of the 16 channels
            int r   = p / HCX;
            int col = p - r * HCX;
            int gy  = by + r   - 1;
            int gx  = bx + col - 1;
            float4 xv = make_float4(0.f, 0.f, 0.f, 0.f);
            float4 hv = make_float4(0.f, 0.f, 0.f, 0.f);
            if (gy >= 0 && gy < HH && gx >= 0 && gx < WW) {
                long pixoff = ((long)gy * WW + gx);
                xv = *(const float4*)(x    + xbase + pixoff * CIN + c4 * 4);
                hv = *(const float4*)(h_in + hbase + pixoff * FF  + c4 * 4);
            }
            int cb = c4 * 4;
            sx[(cb + 0) * PLANE + p] = xv.x;
            sx[(cb + 1) * PLANE + p] = xv.y;
            sx[(cb + 2) * PLANE + p] = xv.z;
            sx[(cb + 3) * PLANE + p] = xv.w;
            sh[(cb + 0) * PLANE + p] = hv.x;
            sh[(cb + 1) * PLANE + p] = hv.y;
            sh[(cb + 2) * PLANE + p] = hv.z;
            sh[(cb + 3) * PLANE + p] = hv.w;
        }
    }
    __syncthreads();

    // ---- accumulate 64 gate pre-activations for this thread's pixel ----
    float acc[GG];
    #pragma unroll
    for (int j = 0; j < GG; j++) acc[j] = 0.f;

    #pragma unroll 1
    for (int ky = 0; ky < 3; ky++) {
        #pragma unroll 1
        for (int kx = 0; kx < 3; kx++) {
            const int   poff = (ty + ky) * HCX + (tx + kx);
            const float* xp  = sx + poff;
            const float* hp  = sh + poff;
            const float4* wxt = (const float4*)(swx + (ky * 3 + kx) * CIN * GG);
            const float4* wht = (const float4*)(swh + (ky * 3 + kx) * CIN * GG);
            #pragma unroll 1
            for (int ci = 0; ci < CIN; ci++) {
                const float xv = xp[ci * PLANE];
                const float hv = hp[ci * PLANE];
                const float4* wx4 = wxt + ci * (GG / 4);
                const float4* wh4 = wht + ci * (GG / 4);
                #pragma unroll
                for (int q = 0; q < GG / 4; q++) {
                    float4 a = wx4[q];
                    float4 c = wh4[q];
                    acc[4*q+0] = fmaf(xv, a.x, acc[4*q+0]);
                    acc[4*q+1] = fmaf(xv, a.y, acc[4*q+1]);
                    acc[4*q+2] = fmaf(xv, a.z, acc[4*q+2]);
                    acc[4*q+3] = fmaf(xv, a.w, acc[4*q+3]);
                    acc[4*q+0] = fmaf(hv, c.x, acc[4*q+0]);
                    acc[4*q+1] = fmaf(hv, c.y, acc[4*q+1]);
                    acc[4*q+2] = fmaf(hv, c.z, acc[4*q+2]);
                    acc[4*q+3] = fmaf(hv, c.w, acc[4*q+3]);
                }
            }
        }
    }

    // ---- gates + state update ----
    const int gy = by + ty;
    const int gx = bx + tx;
    const long pbase = (((long)b * HH + gy) * WW + gx) * FF;

    float cprev[FF];
    {
        const float4* cp4 = (const float4*)(c_state + pbase);
        #pragma unroll
        for (int j = 0; j < 4; j++) {
            float4 v = cp4[j];
            cprev[4*j+0] = v.x; cprev[4*j+1] = v.y;
            cprev[4*j+2] = v.z; cprev[4*j+3] = v.w;
        }
    }

    float cnew[FF], hnew[FF];
    #pragma unroll
    for (int k = 0; k < FF; k++) {
        float zi = acc[k]          + __ldg(bias + k);
        float zf = acc[FF + k]     + __ldg(bias + FF + k);
        float zc = acc[2 * FF + k] + __ldg(bias + 2 * FF + k);
        float zo = acc[3 * FF + k] + __ldg(bias + 3 * FF + k);
        float ig = 1.f / (1.f + expf(-zi));
        float fg = 1.f / (1.f + expf(-zf));
        float og = 1.f / (1.f + expf(-zo));
        float cc = fg * cprev[k] + ig * fmaxf(zc, 0.f);
        cnew[k] = cc;
        hnew[k] = og * fmaxf(cc, 0.f);
    }

    {
        float4* cp4 = (float4*)(c_state + pbase);
        float4* hp4 = (float4*)(h_out + pbase);
        #pragma unroll
        for (int j = 0; j < 4; j++) {
            cp4[j] = make_float4(cnew[4*j], cnew[4*j+1], cnew[4*j+2], cnew[4*j+3]);
            hp4[j] = make_float4(hnew[4*j], hnew[4*j+1], hnew[4*j+2], hnew[4*j+3]);
        }
    }
}

__global__ void dense_kernel(const float* __restrict__ hbuf,
                             const float* __restrict__ dw,
                             const float* __restrict__ db,
                             float* __restrict__ out)
{
    int idx = blockIdx.x * blockDim.x + threadIdx.x;
    if (idx >= BB * HH * WW) return;
    const float4* hp = (const float4*)(hbuf + (long)idx * FF);
    float s = 0.f;
    #pragma unroll
    for (int j = 0; j < 4; j++) {
        float4 v = hp[j];
        s += v.x * __ldg(dw + 4*j + 0);
        s += v.y * __ldg(dw + 4*j + 1);
        s += v.z * __ldg(dw + 4*j + 2);
        s += v.w * __ldg(dw + 4*j + 3);
    }
    out[idx] = s + __ldg(db);
}

extern "C" void kernel_launch(void* const* d_in, const int* in_sizes, int n_in,
                              void* d_out, int out_size)
{
    (void)in_sizes; (void)n_in; (void)out_size;
    const float* x    = (const float*)d_in[0];  // (B,T,H,W,Cin)
    const float* wx   = (const float*)d_in[1];  // (3,3,16,64)
    const float* wh   = (const float*)d_in[2];  // (3,3,16,64)
    const float* bias = (const float*)d_in[3];  // (64,)
    const float* dw   = (const float*)d_in[4];  // (16,1)
    const float* db   = (const float*)d_in[5];  // (1,)
    float* out = (float*)d_out;

    cudaFuncSetAttribute(lstm_step_kernel,
                         cudaFuncAttributeMaxDynamicSharedMemorySize, SMEM_BYTES);

    float* hbuf;  // g_h base
    float* cbuf;
    cudaGetSymbolAddress((void**)&hbuf, g_h);
    cudaGetSymbolAddress((void**)&cbuf, g_c);
    float* h0 = hbuf;
    float* h1 = hbuf + STATE_ELEMS;

    zero_state_kernel<<<512, 256>>>();

    dim3 grid(WW / TLX, HH / TLY, BB);   // (3, 6, 16)
    dim3 block(TLX, TLY);                // (32, 16)

    for (int t = 0; t < TT; t++) {
        float* hin  = (t & 1) ? h1 : h0;
        float* hout = (t & 1) ? h0 : h1;
        lstm_step_kernel<<<grid, block, SMEM_BYTES>>>(
            x, wx, wh, bias, hin, hout, cbuf, t);
    }

    // after t=23 (odd), last h is in h0
    int npix = BB * HH * WW;
    dense_kernel<<<(npix + 255) / 256, 256>>>(h0, dw, db, out);
}

// round 2
// speedup vs baseline: 1.5948x; 1.5948x over previous
#include <cuda_runtime.h>
#include <math.h>

#define BB   16
#define TT   24
#define HH   96
#define WW   96
#define CIN  16
#define FF   16
#define GG   64   // 4*FF gate channels

// spatial tile: 32 x 8 pixels, 2 channel-halves -> 512 threads
#define TLX  32
#define TLY  8
#define HCX  (TLX + 2)    // 34
#define HCY  (TLY + 2)    // 10
#define PLANE (HCY * HCX) // 340 floats per channel plane
#define NPIX (TLX * TLY)  // 256

#define STATE_ELEMS (BB * HH * WW * FF)
#define WSZ (9 * CIN * GG)   // 9216 floats per weight tensor

// scratch state (device globals: no allocation allowed in kernel_launch)
__device__ __align__(16) float g_h[2][STATE_ELEMS];
__device__ __align__(16) float g_c[STATE_ELEMS];

// smem layout (floats): [ swx: WSZ ][ swh: WSZ ][ sx: 16*PLANE ][ sh: 16*PLANE ]
// z-exchange buffer (32*NPIX = 8192 floats) is overlaid on sx..sh after accumulate.
#define SMEM_FLOATS (2 * WSZ + 2 * CIN * PLANE)
#define SMEM_BYTES  (SMEM_FLOATS * 4)   // 117248 B

__global__ void zero_state_kernel() {
    int n = STATE_ELEMS;
    for (int i = blockIdx.x * blockDim.x + threadIdx.x; i < n;
         i += gridDim.x * blockDim.x) {
        g_h[0][i] = 0.f;
        g_c[i]    = 0.f;
    }
}

__device__ __forceinline__ unsigned long long pack2(float v) {
    unsigned long long r;
    asm("mov.b64 %0, {%1, %1};" : "=l"(r) : "f"(v));
    return r;
}
__device__ __forceinline__ void fma2(unsigned long long& d,
                                     unsigned long long a,
                                     unsigned long long b) {
    asm("fma.rn.f32x2 %0, %1, %2, %0;" : "+l"(d) : "l"(a), "l"(b));
}
__device__ __forceinline__ float2 unpack2(unsigned long long v) {
    float2 f;
    asm("mov.b64 {%0, %1}, %2;" : "=f"(f.x), "=f"(f.y) : "l"(v));
    return f;
}

__global__ __launch_bounds__(512, 1)
void lstm_step_kernel(const float* __restrict__ x,
                      const float* __restrict__ wx,
                      const float* __restrict__ wh,
                      const float* __restrict__ bias,
                      const float* __restrict__ h_in,
                      float* __restrict__ h_out,
                      float* __restrict__ c_state,
                      int t)
{
    extern __shared__ float smem[];
    float* swx = smem;                  // WSZ
    float* swh = swx + WSZ;             // WSZ
    float* sx  = swh + WSZ;             // 16*PLANE
    float* sh  = sx  + CIN * PLANE;     // 16*PLANE
    float* zbuf = sx;                   // overlay: 32*NPIX floats (fits in sx+sh)

    const int tx  = threadIdx.x;        // 0..31
    const int ty  = threadIdx.y;        // 0..7
    const int tz  = threadIdx.z;        // 0..1 (channel half)
    const int tid = (tz * TLY + ty) * TLX + tx;  // 0..511
    const int bx  = blockIdx.x * TLX;
    const int by  = blockIdx.y * TLY;
    const int b   = blockIdx.z;

    // ---- stage weights to smem (vector copies) ----
    {
        const float4* wx4 = (const float4*)wx;
        const float4* wh4 = (const float4*)wh;
        float4* swx4 = (float4*)swx;
        float4* swh4 = (float4*)swh;
        #pragma unroll 1
        for (int i = tid; i < WSZ / 4; i += 512) {
            swx4[i] = wx4[i];
            swh4[i] = wh4[i];
        }
    }

    // ---- stage x tile + halo and h tile + halo (channel-major planes) ----
    {
        const long xbase = ((long)(b * TT + t)) * (HH * WW * CIN);
        const long hbase = ((long)b) * (HH * WW * FF);
        #pragma unroll 1
        for (int i = tid; i < PLANE * 4; i += 512) {
            int p   = i >> 2;
            int c4  = i & 3;
            int r   = p / HCX;
            int col = p - r * HCX;
            int gy  = by + r   - 1;
            int gx  = bx + col - 1;
            float4 xv = make_float4(0.f, 0.f, 0.f, 0.f);
            float4 hv = make_float4(0.f, 0.f, 0.f, 0.f);
            if (gy >= 0 && gy < HH && gx >= 0 && gx < WW) {
                long pixoff = ((long)gy * WW + gx);
                xv = *(const float4*)(x    + xbase + pixoff * CIN + c4 * 4);
                hv = *(const float4*)(h_in + hbase + pixoff * FF  + c4 * 4);
            }
            int cb = c4 * 4;
            sx[(cb + 0) * PLANE + p] = xv.x;
            sx[(cb + 1) * PLANE + p] = xv.y;
            sx[(cb + 2) * PLANE + p] = xv.z;
            sx[(cb + 3) * PLANE + p] = xv.w;
            sh[(cb + 0) * PLANE + p] = hv.x;
            sh[(cb + 1) * PLANE + p] = hv.y;
            sh[(cb + 2) * PLANE + p] = hv.z;
            sh[(cb + 3) * PLANE + p] = hv.w;
        }
    }
    __syncthreads();

    // ---- accumulate 32 gate pre-activations (this half) via packed f32x2 ----
    unsigned long long acc[16];
    #pragma unroll
    for (int j = 0; j < 16; j++) acc[j] = 0ull;

    const int chbase = tz * 32;   // this thread's channel range [chbase, chbase+32)

    #pragma unroll 1
    for (int ky = 0; ky < 3; ky++) {
        #pragma unroll 1
        for (int kx = 0; kx < 3; kx++) {
            const int poff = (ty + ky) * HCX + (tx + kx);
            const float* xp = sx + poff;
            const float* hp = sh + poff;
            const ulonglong2* wxt =
                (const ulonglong2*)(swx + (ky * 3 + kx) * CIN * GG + chbase);
            const ulonglong2* wht =
                (const ulonglong2*)(swh + (ky * 3 + kx) * CIN * GG + chbase);
            #pragma unroll 4
            for (int ci = 0; ci < CIN; ci++) {
                const float xv = xp[ci * PLANE];
                const float hv = hp[ci * PLANE];
                unsigned long long xv2 = pack2(xv);
                unsigned long long hv2 = pack2(hv);
                const ulonglong2* wxp = wxt + ci * (GG / 4);
                const ulonglong2* whp = wht + ci * (GG / 4);
                #pragma unroll
                for (int q = 0; q < 8; q++) {
                    ulonglong2 a = wxp[q];
                    ulonglong2 c = whp[q];
                    fma2(acc[2 * q + 0], xv2, a.x);
                    fma2(acc[2 * q + 1], xv2, a.y);
                    fma2(acc[2 * q + 0], hv2, c.x);
                    fma2(acc[2 * q + 1], hv2, c.y);
                }
            }
        }
    }

    float accf[32];
    #pragma unroll
    for (int j = 0; j < 16; j++) {
        float2 v = unpack2(acc[j]);
        accf[2 * j + 0] = v.x;
        accf[2 * j + 1] = v.y;
    }

    const int pix = ty * TLX + tx;   // 0..255

    __syncthreads();   // everyone done reading sx/sh; zbuf overlay now safe

    // ---- half 1 (zc, zo channels 32..63) publishes to smem ----
    if (tz == 1) {
        #pragma unroll
        for (int chl = 0; chl < 32; chl++) {
            zbuf[chl * NPIX + pix] = accf[chl] + __ldg(bias + 32 + chl);
        }
    }
    __syncthreads();

    // ---- half 0 (zi, zf channels 0..31) does the state update ----
    if (tz == 0) {
        const int gy = by + ty;
        const int gx = bx + tx;
        const long pbase = (((long)b * HH + gy) * WW + gx) * FF;

        float cprev[FF];
        {
            const float4* cp4 = (const float4*)(c_state + pbase);
            #pragma unroll
            for (int j = 0; j < 4; j++) {
                float4 v = cp4[j];
                cprev[4*j+0] = v.x; cprev[4*j+1] = v.y;
                cprev[4*j+2] = v.z; cprev[4*j+3] = v.w;
            }
        }

        float cnew[FF], hnew[FF];
        #pragma unroll
        for (int k = 0; k < FF; k++) {
            float zi = accf[k]      + __ldg(bias + k);
            float zf = accf[16 + k] + __ldg(bias + 16 + k);
            float zc = zbuf[k * NPIX + pix];          // ch 32+k
            float zo = zbuf[(16 + k) * NPIX + pix];   // ch 48+k
            float ig = 1.f / (1.f + __expf(-zi));
            float fg = 1.f / (1.f + __expf(-zf));
            float og = 1.f / (1.f + __expf(-zo));
            float cc = fg * cprev[k] + ig * fmaxf(zc, 0.f);
            cnew[k] = cc;
            hnew[k] = og * fmaxf(cc, 0.f);
        }

        float4* cp4 = (float4*)(c_state + pbase);
        float4* hp4 = (float4*)(h_out + pbase);
        #pragma unroll
        for (int j = 0; j < 4; j++) {
            cp4[j] = make_float4(cnew[4*j], cnew[4*j+1], cnew[4*j+2], cnew[4*j+3]);
            hp4[j] = make_float4(hnew[4*j], hnew[4*j+1], hnew[4*j+2], hnew[4*j+3]);
        }
    }
}

__global__ void dense_kernel(const float* __restrict__ hbuf,
                             const float* __restrict__ dw,
                             const float* __restrict__ db,
                             float* __restrict__ out)
{
    int idx = blockIdx.x * blockDim.x + threadIdx.x;
    if (idx >= BB * HH * WW) return;
    const float4* hp = (const float4*)(hbuf + (long)idx * FF);
    float s = 0.f;
    #pragma unroll
    for (int j = 0; j < 4; j++) {
        float4 v = hp[j];
        s += v.x * __ldg(dw + 4*j + 0);
        s += v.y * __ldg(dw + 4*j + 1);
        s += v.z * __ldg(dw + 4*j + 2);
        s += v.w * __ldg(dw + 4*j + 3);
    }
    out[idx] = s + __ldg(db);
}

extern "C" void kernel_launch(void* const* d_in, const int* in_sizes, int n_in,
                              void* d_out, int out_size)
{
    (void)in_sizes; (void)n_in; (void)out_size;
    const float* x    = (const float*)d_in[0];  // (B,T,H,W,Cin)
    const float* wx   = (const float*)d_in[1];  // (3,3,16,64)
    const float* wh   = (const float*)d_in[2];  // (3,3,16,64)
    const float* bias = (const float*)d_in[3];  // (64,)
    const float* dw   = (const float*)d_in[4];  // (16,1)
    const float* db   = (const float*)d_in[5];  // (1,)
    float* out = (float*)d_out;

    cudaFuncSetAttribute(lstm_step_kernel,
                         cudaFuncAttributeMaxDynamicSharedMemorySize, SMEM_BYTES);

    float* hbuf;
    float* cbuf;
    cudaGetSymbolAddress((void**)&hbuf, g_h);
    cudaGetSymbolAddress((void**)&cbuf, g_c);
    float* h0 = hbuf;
    float* h1 = hbuf + STATE_ELEMS;

    zero_state_kernel<<<512, 256>>>();

    dim3 grid(WW / TLX, HH / TLY, BB);   // (3, 12, 16)
    dim3 block(TLX, TLY, 2);             // (32, 8, 2)

    for (int t = 0; t < TT; t++) {
        float* hin  = (t & 1) ? h1 : h0;
        float* hout = (t & 1) ? h0 : h1;
        lstm_step_kernel<<<grid, block, SMEM_BYTES>>>(
            x, wx, wh, bias, hin, hout, cbuf, t);
    }

    // after t=23 (odd), last h is in h0
    int npix = BB * HH * WW;
    dense_kernel<<<(npix + 255) / 256, 256>>>(h0, dw, db, out);
}

// round 4
// speedup vs baseline: 4.7315x; 2.9669x over previous
#include <cuda_runtime.h>
#include <cuda_fp16.h>
#include <cstdint>
#include <math.h>

#define BB   16
#define TT   24
#define HH   96
#define WW   96
#define CIN  16
#define FF   16
#define GG   64

#define TLX  32
#define TLY  8
#define STATE_ELEMS (BB * HH * WW * FF)
#define XN (BB * TT * HH * WW * CIN)

// ---------------- device global scratch ----------------
__device__ __align__(16) __half g_xhi[XN];
__device__ __align__(16) __half g_xlo[XN];
__device__ __align__(16) __half g_hh[2][STATE_ELEMS];
__device__ __align__(16) __half g_hl[2][STATE_ELEMS];
__device__ __align__(16) float  g_c[STATE_ELEMS];
// B fragments: [kstep 18][ntile 8][part 2][lane 32][reg 2] half2-words
#define BFRAG_WORDS (18 * 8 * 2 * 32 * 2)   // 18432
__device__ __align__(16) uint32_t g_bfrag[BFRAG_WORDS];

// ---------------- smem layout (bytes) ----------------
// [0 : 73728)            B fragments (kstep*4096 + nt*512 + part*256 + lane*8 + reg*4)
// [73728 : +4*10880)     strips: xhi, xlo, hhi, hlo ; each [row 10][col 34][ci 16] fp16
#define SMEM_BF     0
#define BF_BYTES    73728
#define STRIP_BYTES (10 * 34 * CIN * 2)     // 10880
#define SMEM_STRIP  BF_BYTES
#define SMEM_TOTAL  (BF_BYTES + 4 * STRIP_BYTES)   // 117248

// ---------------- mma helper ----------------
__device__ __forceinline__ void mma16816(float* d, const uint32_t* a,
                                         const uint32_t* b) {
    asm volatile(
        "mma.sync.aligned.m16n8k16.row.col.f32.f16.f16.f32 "
        "{%0,%1,%2,%3}, {%4,%5,%6,%7}, {%8,%9}, {%0,%1,%2,%3};"
        : "+f"(d[0]), "+f"(d[1]), "+f"(d[2]), "+f"(d[3])
        : "r"(a[0]), "r"(a[1]), "r"(a[2]), "r"(a[3]), "r"(b[0]), "r"(b[1]));
}

// ---------------- setup kernels ----------------
__global__ void convert_x_kernel(const float* __restrict__ x) {
    for (long i = blockIdx.x * (long)blockDim.x + threadIdx.x; i < XN;
         i += (long)gridDim.x * blockDim.x) {
        float v = x[i];
        __half hi = __float2half_rn(v);
        __half lo = __float2half_rn(v - __half2float(hi));
        g_xhi[i] = hi;
        g_xlo[i] = lo;
    }
}

__global__ void zero_state_kernel() {
    __half z = __float2half_rn(0.f);
    for (int i = blockIdx.x * blockDim.x + threadIdx.x; i < STATE_ELEMS;
         i += gridDim.x * blockDim.x) {
        g_hh[0][i] = z;
        g_hl[0][i] = z;
        g_c[i] = 0.f;
    }
}

__global__ void bfrag_kernel(const float* __restrict__ wx,
                             const float* __restrict__ wh) {
    int idx = blockIdx.x * blockDim.x + threadIdx.x;
    if (idx >= BFRAG_WORDS) return;
    int reg   = idx & 1;
    int lane  = (idx >> 1) & 31;
    int part  = (idx >> 6) & 1;
    int nt    = (idx >> 7) & 7;
    int kstep = idx >> 10;
    int j = lane & 3;
    int n = nt * 8 + (lane >> 2);
    int k0 = reg * 8 + 2 * j;
    const float* W = (kstep < 9) ? wx : wh;
    int tap = (kstep < 9) ? kstep : kstep - 9;
    float v0 = W[(tap * 16 + k0) * 64 + n];
    float v1 = W[(tap * 16 + k0 + 1) * 64 + n];
    __half h0 = __float2half_rn(v0);
    __half h1 = __float2half_rn(v1);
    __half o0, o1;
    if (part == 0) { o0 = h0; o1 = h1; }
    else {
        o0 = __float2half_rn(v0 - __half2float(h0));
        o1 = __float2half_rn(v1 - __half2float(h1));
    }
    uint32_t w = (uint32_t)__half_as_ushort(o0) |
                 ((uint32_t)__half_as_ushort(o1) << 16);
    g_bfrag[idx] = w;
}

// ---------------- main step kernel ----------------
__global__ __launch_bounds__(512, 1)
void lstm_step_mma(const float* __restrict__ bias,
                   const __half* __restrict__ hh_in,
                   const __half* __restrict__ hl_in,
                   __half* __restrict__ hh_out,
                   __half* __restrict__ hl_out,
                   float* __restrict__ c_state,
                   int t)
{
    extern __shared__ char smem[];
    const int tid  = threadIdx.x;
    const int wid  = tid >> 5;
    const int lane = tid & 31;
    const int x0 = blockIdx.x * TLX;
    const int y0 = blockIdx.y * TLY;
    const int b  = blockIdx.z;

    // ---- copy B fragments ----
    {
        const uint4* src = (const uint4*)g_bfrag;
        uint4* dst = (uint4*)(smem + SMEM_BF);
        #pragma unroll 1
        for (int i = tid; i < BF_BYTES / 16; i += 512) dst[i] = src[i];
    }

    // ---- stage strips (zero halo) ----
    {
        const long xg = ((long)(b * TT + t)) * (HH * WW * CIN);
        const long hg = ((long)b) * (HH * WW * CIN);
        #pragma unroll 1
        for (int i = tid; i < 4 * 340; i += 512) {
            int comp = i / 340;
            int idx  = i - comp * 340;
            int row  = idx / 34;
            int col  = idx - row * 34;
            int y  = y0 + row - 1;
            int xc = x0 + col - 1;
            uint4 v0 = make_uint4(0, 0, 0, 0), v1 = v0;
            if ((unsigned)y < HH && (unsigned)xc < WW) {
                const __half* base =
                    (comp == 0) ? g_xhi : (comp == 1) ? g_xlo
                  : (comp == 2) ? hh_in : hl_in;
                long off = ((comp < 2) ? xg : hg) + (((long)y) * WW + xc) * CIN;
                const uint4* sp = (const uint4*)(base + off);
                v0 = sp[0];
                v1 = sp[1];
            }
            uint4* dp = (uint4*)(smem + SMEM_STRIP + comp * STRIP_BYTES +
                                 (row * 34 + col) * 32);
            dp[0] = v0;
            dp[1] = v1;
        }
    }
    __syncthreads();

    // ---- per-warp GEMM: m16 pixels x n64 gates, K = 288 (x||h), 3 products ----
    const int mt    = wid;                 // 0..15 M-tiles
    const int prow  = mt >> 1;             // tile row 0..7
    const int pcol0 = (mt & 1) * 16;       // tile col base
    const int g = lane >> 2;
    const int j = lane & 3;

    float d[8][4];
    #pragma unroll
    for (int nt = 0; nt < 8; nt++)
        #pragma unroll
        for (int q = 0; q < 4; q++) d[nt][q] = 0.f;

    #pragma unroll 1
    for (int tensor = 0; tensor < 2; tensor++) {
        const char* shi = smem + SMEM_STRIP + tensor * 2 * STRIP_BYTES;
        const char* slo = shi + STRIP_BYTES;
        #pragma unroll 1
        for (int tap = 0; tap < 9; tap++) {
            const int dy = tap / 3;
            const int dx = tap - dy * 3;
            const int off = ((prow + dy) * 34 + (pcol0 + dx)) * 32;

            uint32_t ah[4], al[4];
            ah[0] = *(const uint32_t*)(shi + off + g * 32 + j * 4);
            ah[1] = *(const uint32_t*)(shi + off + (g + 8) * 32 + j * 4);
            ah[2] = *(const uint32_t*)(shi + off + g * 32 + 16 + j * 4);
            ah[3] = *(const uint32_t*)(shi + off + (g + 8) * 32 + 16 + j * 4);
            al[0] = *(const uint32_t*)(slo + off + g * 32 + j * 4);
            al[1] = *(const uint32_t*)(slo + off + (g + 8) * 32 + j * 4);
            al[2] = *(const uint32_t*)(slo + off + g * 32 + 16 + j * 4);
            al[3] = *(const uint32_t*)(slo + off + (g + 8) * 32 + 16 + j * 4);

            const int kstep = tensor * 9 + tap;
            const char* bb = smem + SMEM_BF + kstep * 4096 + lane * 8;
            #pragma unroll
            for (int nt = 0; nt < 8; nt++) {
                uint2 bh = *(const uint2*)(bb + nt * 512);
                uint2 bl = *(const uint2*)(bb + nt * 512 + 256);
                uint32_t bhr[2] = {bh.x, bh.y};
                uint32_t blr[2] = {bl.x, bl.y};
                mma16816(d[nt], ah, bhr);
                mma16816(d[nt], ah, blr);
                mma16816(d[nt], al, bhr);
            }
        }
    }

    // ---- epilogue: LSTM update, fully register-local per lane ----
    const int ybase = y0 + prow;
    #pragma unroll
    for (int ph = 0; ph < 2; ph++) {            // pixel g or g+8
        const int xc = x0 + pcol0 + g + ph * 8;
        const long pb = (((long)b * HH + ybase) * WW + xc) * FF;
        const int co = ph * 2;                  // accumulator index base
        #pragma unroll
        for (int pr = 0; pr < 2; pr++) {        // channel pair A / B
            const int ch  = pr * 8 + 2 * j;     // channels ch, ch+1
            const int ntb = pr;                 // gate ntiles: ntb, ntb+2, +4, +6
            float zi0 = d[ntb][co]       + __ldg(bias + ch);
            float zi1 = d[ntb][co + 1]   + __ldg(bias + ch + 1);
            float zf0 = d[ntb + 2][co]   + __ldg(bias + 16 + ch);
            float zf1 = d[ntb + 2][co+1] + __ldg(bias + 16 + ch + 1);
            float zc0 = d[ntb + 4][co]   + __ldg(bias + 32 + ch);
            float zc1 = d[ntb + 4][co+1] + __ldg(bias + 32 + ch + 1);
            float zo0 = d[ntb + 6][co]   + __ldg(bias + 48 + ch);
            float zo1 = d[ntb + 6][co+1] + __ldg(bias + 48 + ch + 1);

            float2 cp = *(const float2*)(c_state + pb + ch);
            float ig0 = 1.f / (1.f + __expf(-zi0));
            float ig1 = 1.f / (1.f + __expf(-zi1));
            float fg0 = 1.f / (1.f + __expf(-zf0));
            float fg1 = 1.f / (1.f + __expf(-zf1));
            float og0 = 1.f / (1.f + __expf(-zo0));
            float og1 = 1.f / (1.f + __expf(-zo1));
            float cn0 = fg0 * cp.x + ig0 * fmaxf(zc0, 0.f);
            float cn1 = fg1 * cp.y + ig1 * fmaxf(zc1, 0.f);
            float hn0 = og0 * fmaxf(cn0, 0.f);
            float hn1 = og1 * fmaxf(cn1, 0.f);

            *(float2*)(c_state + pb + ch) = make_float2(cn0, cn1);

            __half hh0 = __float2half_rn(hn0);
            __half hh1 = __float2half_rn(hn1);
            __half hl0 = __float2half_rn(hn0 - __half2float(hh0));
            __half hl1 = __float2half_rn(hn1 - __half2float(hh1));
            uint32_t whv = (uint32_t)__half_as_ushort(hh0) |
                           ((uint32_t)__half_as_ushort(hh1) << 16);
            uint32_t wlv = (uint32_t)__half_as_ushort(hl0) |
                           ((uint32_t)__half_as_ushort(hl1) << 16);
            *(uint32_t*)(hh_out + pb + ch) = whv;
            *(uint32_t*)(hl_out + pb + ch) = wlv;
        }
    }
}

// ---------------- dense head ----------------
__global__ void dense_kernel(const __half* __restrict__ hh,
                             const __half* __restrict__ hl,
                             const float* __restrict__ dw,
                             const float* __restrict__ db,
                             float* __restrict__ out)
{
    int idx = blockIdx.x * blockDim.x + threadIdx.x;
    if (idx >= BB * HH * WW) return;
    const __half* hp = hh + (long)idx * FF;
    const __half* lp = hl + (long)idx * FF;
    float sum = 0.f;
    #pragma unroll
    for (int k = 0; k < FF; k++) {
        float h = __half2float(hp[k]) + __half2float(lp[k]);
        sum += h * __ldg(dw + k);
    }
    out[idx] = sum + __ldg(db);
}

extern "C" void kernel_launch(void* const* d_in, const int* in_sizes, int n_in,
                              void* d_out, int out_size)
{
    (void)in_sizes; (void)n_in; (void)out_size;
    const float* x    = (const float*)d_in[0];
    const float* wx   = (const float*)d_in[1];
    const float* wh   = (const float*)d_in[2];
    const float* bias = (const float*)d_in[3];
    const float* dw   = (const float*)d_in[4];
    const float* db   = (const float*)d_in[5];
    float* out = (float*)d_out;

    cudaFuncSetAttribute(lstm_step_mma,
                         cudaFuncAttributeMaxDynamicSharedMemorySize, SMEM_TOTAL);

    __half *hh, *hl;
    float* cbuf;
    cudaGetSymbolAddress((void**)&hh, g_hh);
    cudaGetSymbolAddress((void**)&hl, g_hl);
    cudaGetSymbolAddress((void**)&cbuf, g_c);

    convert_x_kernel<<<2048, 256>>>(x);
    zero_state_kernel<<<512, 256>>>();
    bfrag_kernel<<<(BFRAG_WORDS + 255) / 256, 256>>>(wx, wh);

    dim3 grid(WW / TLX, HH / TLY, BB);   // (3, 12, 16)
    for (int t = 0; t < TT; t++) {
        __half* hhi = hh + (t & 1) * STATE_ELEMS;
        __half* hli = hl + (t & 1) * STATE_ELEMS;
        __half* hho = hh + ((t + 1) & 1) * STATE_ELEMS;
        __half* hlo = hl + ((t + 1) & 1) * STATE_ELEMS;
        lstm_step_mma<<<grid, 512, SMEM_TOTAL>>>(
            bias, hhi, hli, hho, hlo, cbuf, t);
    }

    // t=23 -> final h in buffer index 0
    int npix = BB * HH * WW;
    dense_kernel<<<(npix + 255) / 256, 256>>>(hh, hl, dw, db, out);
}

// round 6
// speedup vs baseline: 5.2633x; 1.1124x over previous
#include <cuda_runtime.h>
#include <cuda_fp16.h>
#include <cstdint>
#include <math.h>

#define BB   16
#define TT   24
#define HH   96
#define WW   96
#define CIN  16
#define FF   16
#define GG   64

#define TLX  32
#define TLY  4
#define STATE_ELEMS (BB * HH * WW * FF)
#define XN (BB * TT * HH * WW * CIN)

// ---------------- device global scratch ----------------
__device__ __align__(16) __half g_xhi[XN];
__device__ __align__(16) __half g_xlo[XN];
__device__ __align__(16) __half g_hh[2][STATE_ELEMS];
__device__ __align__(16) __half g_hl[2][STATE_ELEMS];
__device__ __align__(16) float  g_c[STATE_ELEMS];
// B fragments: [kstep 18][ntile 8][part 2][lane 32][reg 2] half2-words
#define BFRAG_WORDS (18 * 8 * 2 * 32 * 2)   // 18432 (72KB, L1-resident)
__device__ __align__(16) uint32_t g_bfrag[BFRAG_WORDS];

// ---------------- smem layout (bytes) ----------------
// 4 strips: xhi, xlo, hhi, hlo ; each [row 6][col 34][ci 16] fp16, 16B-half
// XOR-swizzled: pixel pi stores its two 16B halves at pi*32 + (half ^ ((pi&4)<<2))
#define STRIP_BYTES (6 * 34 * CIN * 2)      // 6528
#define SMEM_TOTAL  (4 * STRIP_BYTES)       // 26112

// ---------------- mma / ldmatrix helpers ----------------
__device__ __forceinline__ void mma16816(float* d, const uint32_t* a,
                                         const uint32_t* b) {
    asm volatile(
        "mma.sync.aligned.m16n8k16.row.col.f32.f16.f16.f32 "
        "{%0,%1,%2,%3}, {%4,%5,%6,%7}, {%8,%9}, {%0,%1,%2,%3};"
        : "+f"(d[0]), "+f"(d[1]), "+f"(d[2]), "+f"(d[3])
        : "r"(a[0]), "r"(a[1]), "r"(a[2]), "r"(a[3]), "r"(b[0]), "r"(b[1]));
}
__device__ __forceinline__ void ldsm_x4(uint32_t* a, uint32_t addr) {
    asm volatile(
        "ldmatrix.sync.aligned.m8n8.x4.shared.b16 {%0,%1,%2,%3}, [%4];"
        : "=r"(a[0]), "=r"(a[1]), "=r"(a[2]), "=r"(a[3]) : "r"(addr));
}
__device__ __forceinline__ uint32_t smem_u32(const void* p) {
    uint32_t a;
    asm("{ .reg .u64 t; cvta.to.shared.u64 t, %1; cvt.u32.u64 %0, t; }"
        : "=r"(a) : "l"(p));
    return a;
}

// ---------------- setup kernels ----------------
__global__ void convert_x_kernel(const float* __restrict__ x) {
    for (long i = blockIdx.x * (long)blockDim.x + threadIdx.x; i < XN;
         i += (long)gridDim.x * blockDim.x) {
        float v = x[i];
        __half hi = __float2half_rn(v);
        __half lo = __float2half_rn(v - __half2float(hi));
        g_xhi[i] = hi;
        g_xlo[i] = lo;
    }
}

__global__ void zero_state_kernel() {
    __half z = __float2half_rn(0.f);
    for (int i = blockIdx.x * blockDim.x + threadIdx.x; i < STATE_ELEMS;
         i += gridDim.x * blockDim.x) {
        g_hh[0][i] = z;
        g_hl[0][i] = z;
        g_c[i] = 0.f;
    }
}

__global__ void bfrag_kernel(const float* __restrict__ wx,
                             const float* __restrict__ wh) {
    int idx = blockIdx.x * blockDim.x + threadIdx.x;
    if (idx >= BFRAG_WORDS) return;
    int reg   = idx & 1;
    int lane  = (idx >> 1) & 31;
    int part  = (idx >> 6) & 1;
    int nt    = (idx >> 7) & 7;
    int kstep = idx >> 10;
    int j = lane & 3;
    int n = nt * 8 + (lane >> 2);
    int k0 = reg * 8 + 2 * j;
    const float* W = (kstep < 9) ? wx : wh;
    int tap = (kstep < 9) ? kstep : kstep - 9;
    float v0 = W[(tap * 16 + k0) * 64 + n];
    float v1 = W[(tap * 16 + k0 + 1) * 64 + n];
    __half h0 = __float2half_rn(v0);
    __half h1 = __float2half_rn(v1);
    __half o0, o1;
    if (part == 0) { o0 = h0; o1 = h1; }
    else {
        o0 = __float2half_rn(v0 - __half2float(h0));
        o1 = __float2half_rn(v1 - __half2float(h1));
    }
    uint32_t w = (uint32_t)__half_as_ushort(o0) |
                 ((uint32_t)__half_as_ushort(o1) << 16);
    g_bfrag[idx] = w;
}

// ---------------- main step kernel ----------------
__global__ __launch_bounds__(256, 2)
void lstm_step_mma(const float* __restrict__ bias,
                   const __half* __restrict__ hh_in,
                   const __half* __restrict__ hl_in,
                   __half* __restrict__ hh_out,
                   __half* __restrict__ hl_out,
                   float* __restrict__ c_state,
                   int t)
{
    extern __shared__ char smem[];
    const uint32_t sb = smem_u32(smem);
    const int tid  = threadIdx.x;
    const int wid  = tid >> 5;
    const int lane = tid & 31;
    const int x0 = blockIdx.x * TLX;
    const int y0 = blockIdx.y * TLY;
    const int b  = blockIdx.z;

    // ---- stage strips (zero halo), XOR-swizzled 16B halves ----
    {
        const long xg = ((long)(b * TT + t)) * (HH * WW * CIN);
        const long hg = ((long)b) * (HH * WW * CIN);
        #pragma unroll 1
        for (int i = tid; i < 4 * 6 * 34; i += 256) {
            int comp = i / 204;
            int idx  = i - comp * 204;
            int row  = idx / 34;
            int col  = idx - row * 34;
            int y  = y0 + row - 1;
            int xc = x0 + col - 1;
            uint4 v0 = make_uint4(0, 0, 0, 0), v1 = v0;
            if ((unsigned)y < HH && (unsigned)xc < WW) {
                const __half* base =
                    (comp == 0) ? g_xhi : (comp == 1) ? g_xlo
                  : (comp == 2) ? hh_in : hl_in;
                long off = ((comp < 2) ? xg : hg) + (((long)y) * WW + xc) * CIN;
                const uint4* sp = (const uint4*)(base + off);
                v0 = sp[0];
                v1 = sp[1];
            }
            int pi = row * 34 + col;
            int sw = (pi & 4) << 2;   // 0 or 16
            char* dp = smem + comp * STRIP_BYTES + pi * 32;
            *(uint4*)(dp + (0  ^ sw)) = v0;
            *(uint4*)(dp + (16 ^ sw)) = v1;
        }
    }
    __syncthreads();

    // ---- per-warp GEMM: m16 pixels x n64 gates, K = 288 (x||h), 3 products ----
    const int mt    = wid;                 // 0..7 M-tiles
    const int prow  = mt >> 1;             // tile row 0..3
    const int pcol0 = (mt & 1) * 16;       // tile col base
    const int g = lane >> 2;
    const int j = lane & 3;
    const int lcol  = lane & 15;           // ldmatrix pixel within tile
    const int koff0 = lane & 16;           // ldmatrix k-half (bytes)

    float d[8][4];
    #pragma unroll
    for (int nt = 0; nt < 8; nt++)
        #pragma unroll
        for (int q = 0; q < 4; q++) d[nt][q] = 0.f;

    #pragma unroll 1
    for (int tensor = 0; tensor < 2; tensor++) {
        const uint32_t shi = sb + tensor * 2 * STRIP_BYTES;
        #pragma unroll 1
        for (int tap = 0; tap < 9; tap++) {
            const int dy = tap / 3;
            const int dx = tap - dy * 3;
            const int pi = (prow + dy) * 34 + (pcol0 + dx + lcol);
            const uint32_t aoff =
                (uint32_t)(pi * 32 + (koff0 ^ ((pi & 4) << 2)));

            uint32_t ah[4], al[4];
            ldsm_x4(ah, shi + aoff);
            ldsm_x4(al, shi + STRIP_BYTES + aoff);

            const int kstep = tensor * 9 + tap;
            const char* bb = (const char*)g_bfrag + kstep * 4096 + lane * 8;
            #pragma unroll
            for (int nt = 0; nt < 8; nt++) {
                uint2 bh = __ldg((const uint2*)(bb + nt * 512));
                uint2 bl = __ldg((const uint2*)(bb + nt * 512 + 256));
                uint32_t bhr[2] = {bh.x, bh.y};
                uint32_t blr[2] = {bl.x, bl.y};
                mma16816(d[nt], ah, bhr);
                mma16816(d[nt], ah, blr);
                mma16816(d[nt], al, bhr);
            }
        }
    }

    // ---- epilogue: LSTM update, fully register-local per lane ----
    const int ybase = y0 + prow;
    #pragma unroll
    for (int ph = 0; ph < 2; ph++) {            // pixel g or g+8
        const int xc = x0 + pcol0 + g + ph * 8;
        const long pb = (((long)b * HH + ybase) * WW + xc) * FF;
        const int co = ph * 2;                  // accumulator index base
        #pragma unroll
        for (int pr = 0; pr < 2; pr++) {        // channel pair A / B
            const int ch  = pr * 8 + 2 * j;     // channels ch, ch+1
            const int ntb = pr;                 // gate ntiles: ntb, ntb+2, +4, +6
            float zi0 = d[ntb][co]       + __ldg(bias + ch);
            float zi1 = d[ntb][co + 1]   + __ldg(bias + ch + 1);
            float zf0 = d[ntb + 2][co]   + __ldg(bias + 16 + ch);
            float zf1 = d[ntb + 2][co+1] + __ldg(bias + 16 + ch + 1);
            float zc0 = d[ntb + 4][co]   + __ldg(bias + 32 + ch);
            float zc1 = d[ntb + 4][co+1] + __ldg(bias + 32 + ch + 1);
            float zo0 = d[ntb + 6][co]   + __ldg(bias + 48 + ch);
            float zo1 = d[ntb + 6][co+1] + __ldg(bias + 48 + ch + 1);

            float2 cp = *(const float2*)(c_state + pb + ch);
            float ig0 = 1.f / (1.f + __expf(-zi0));
            float ig1 = 1.f / (1.f + __expf(-zi1));
            float fg0 = 1.f / (1.f + __expf(-zf0));
            float fg1 = 1.f / (1.f + __expf(-zf1));
            float og0 = 1.f / (1.f + __expf(-zo0));
            float og1 = 1.f / (1.f + __expf(-zo1));
            float cn0 = fg0 * cp.x + ig0 * fmaxf(zc0, 0.f);
            float cn1 = fg1 * cp.y + ig1 * fmaxf(zc1, 0.f);
            float hn0 = og0 * fmaxf(cn0, 0.f);
            float hn1 = og1 * fmaxf(cn1, 0.f);

            *(float2*)(c_state + pb + ch) = make_float2(cn0, cn1);

            __half hh0 = __float2half_rn(hn0);
            __half hh1 = __float2half_rn(hn1);
            __half hl0 = __float2half_rn(hn0 - __half2float(hh0));
            __half hl1 = __float2half_rn(hn1 - __half2float(hh1));
            uint32_t whv = (uint32_t)__half_as_ushort(hh0) |
                           ((uint32_t)__half_as_ushort(hh1) << 16);
            uint32_t wlv = (uint32_t)__half_as_ushort(hl0) |
                           ((uint32_t)__half_as_ushort(hl1) << 16);
            *(uint32_t*)(hh_out + pb + ch) = whv;
            *(uint32_t*)(hl_out + pb + ch) = wlv;
        }
    }
}

// ---------------- dense head ----------------
__global__ void dense_kernel(const __half* __restrict__ hh,
                             const __half* __restrict__ hl,
                             const float* __restrict__ dw,
                             const float* __restrict__ db,
                             float* __restrict__ out)
{
    int idx = blockIdx.x * blockDim.x + threadIdx.x;
    if (idx >= BB * HH * WW) return;
    const __half* hp = hh + (long)idx * FF;
    const __half* lp = hl + (long)idx * FF;
    float sum = 0.f;
    #pragma unroll
    for (int k = 0; k < FF; k++) {
        float h = __half2float(hp[k]) + __half2float(lp[k]);
        sum += h * __ldg(dw + k);
    }
    out[idx] = sum + __ldg(db);
}

extern "C" void kernel_launch(void* const* d_in, const int* in_sizes, int n_in,
                              void* d_out, int out_size)
{
    (void)in_sizes; (void)n_in; (void)out_size;
    const float* x    = (const float*)d_in[0];
    const float* wx   = (const float*)d_in[1];
    const float* wh   = (const float*)d_in[2];
    const float* bias = (const float*)d_in[3];
    const float* dw   = (const float*)d_in[4];
    const float* db   = (const float*)d_in[5];
    float* out = (float*)d_out;

    __half *hh, *hl;
    float* cbuf;
    cudaGetSymbolAddress((void**)&hh, g_hh);
    cudaGetSymbolAddress((void**)&hl, g_hl);
    cudaGetSymbolAddress((void**)&cbuf, g_c);

    convert_x_kernel<<<2048, 256>>>(x);
    zero_state_kernel<<<512, 256>>>();
    bfrag_kernel<<<(BFRAG_WORDS + 255) / 256, 256>>>(wx, wh);

    dim3 grid(WW / TLX, HH / TLY, BB);   // (3, 24, 16)
    for (int t = 0; t < TT; t++) {
        __half* hhi = hh + (t & 1) * STATE_ELEMS;
        __half* hli = hl + (t & 1) * STATE_ELEMS;
        __half* hho = hh + ((t + 1) & 1) * STATE_ELEMS;
        __half* hlo = hl + ((t + 1) & 1) * STATE_ELEMS;
        lstm_step_mma<<<grid, 256, SMEM_TOTAL>>>(
            bias, hhi, hli, hho, hlo, cbuf, t);
    }

    // t=23 -> final h in buffer index 0
    int npix = BB * HH * WW;
    dense_kernel<<<(npix + 255) / 256, 256>>>(hh, hl, dw, db, out);
}

// round 7
// speedup vs baseline: 6.1708x; 1.1724x over previous
#include <cuda_runtime.h>
#include <cuda_fp16.h>
#include <cstdint>
#include <math.h>

#define BB   16
#define TT   24
#define HH   96
#define WW   96
#define CIN  16
#define FF   16
#define GG   64

#define TLX  32
#define TLY  8
#define STATE_ELEMS (BB * HH * WW * FF)
#define XN (BB * TT * HH * WW * CIN)

// ---------------- device global scratch ----------------
__device__ __align__(16) __half g_xhi[XN];
__device__ __align__(16) __half g_xlo[XN];
__device__ __align__(16) __half g_hh[2][STATE_ELEMS];
__device__ __align__(16) __half g_hl[2][STATE_ELEMS];
__device__ __align__(16) float  g_c[STATE_ELEMS];
// B fragments: [kstep 18][ntile 8][part 2][lane 32][reg 2] half2-words
#define BFRAG_WORDS (18 * 8 * 2 * 32 * 2)   // 18432 (72KB, L1-resident)
__device__ __align__(16) uint32_t g_bfrag[BFRAG_WORDS];

// ---------------- smem layout (bytes) ----------------
// 4 strips: xhi, xlo, hhi, hlo ; each [row 10][col 34][ci 16] fp16
// XOR-swizzled: pixel pi stores its two 16B halves at pi*32 + (half ^ ((pi&4)<<2))
#define STRIP_BYTES (10 * 34 * CIN * 2)     // 10880
#define SMEM_TOTAL  (4 * STRIP_BYTES)       // 43520

// ---------------- mma / ldmatrix helpers ----------------
__device__ __forceinline__ void mma16816(float* d, const uint32_t* a,
                                         const uint32_t* b) {
    asm volatile(
        "mma.sync.aligned.m16n8k16.row.col.f32.f16.f16.f32 "
        "{%0,%1,%2,%3}, {%4,%5,%6,%7}, {%8,%9}, {%0,%1,%2,%3};"
        : "+f"(d[0]), "+f"(d[1]), "+f"(d[2]), "+f"(d[3])
        : "r"(a[0]), "r"(a[1]), "r"(a[2]), "r"(a[3]), "r"(b[0]), "r"(b[1]));
}
__device__ __forceinline__ void ldsm_x4(uint32_t* a, uint32_t addr) {
    asm volatile(
        "ldmatrix.sync.aligned.m8n8.x4.shared.b16 {%0,%1,%2,%3}, [%4];"
        : "=r"(a[0]), "=r"(a[1]), "=r"(a[2]), "=r"(a[3]) : "r"(addr));
}
__device__ __forceinline__ uint32_t smem_u32(const void* p) {
    uint32_t a;
    asm("{ .reg .u64 t; cvta.to.shared.u64 t, %1; cvt.u32.u64 %0, t; }"
        : "=r"(a) : "l"(p));
    return a;
}

// ---------------- setup kernels ----------------
__global__ void convert_x_kernel(const float* __restrict__ x) {
    for (long i = blockIdx.x * (long)blockDim.x + threadIdx.x; i < XN;
         i += (long)gridDim.x * blockDim.x) {
        float v = x[i];
        __half hi = __float2half_rn(v);
        __half lo = __float2half_rn(v - __half2float(hi));
        g_xhi[i] = hi;
        g_xlo[i] = lo;
    }
}

__global__ void zero_state_kernel() {
    __half z = __float2half_rn(0.f);
    for (int i = blockIdx.x * blockDim.x + threadIdx.x; i < STATE_ELEMS;
         i += gridDim.x * blockDim.x) {
        g_hh[0][i] = z;
        g_hl[0][i] = z;
        g_c[i] = 0.f;
    }
}

__global__ void bfrag_kernel(const float* __restrict__ wx,
                             const float* __restrict__ wh) {
    int idx = blockIdx.x * blockDim.x + threadIdx.x;
    if (idx >= BFRAG_WORDS) return;
    int reg   = idx & 1;
    int lane  = (idx >> 1) & 31;
    int part  = (idx >> 6) & 1;
    int nt    = (idx >> 7) & 7;
    int kstep = idx >> 10;
    int j = lane & 3;
    int n = nt * 8 + (lane >> 2);
    int k0 = reg * 8 + 2 * j;
    const float* W = (kstep < 9) ? wx : wh;
    int tap = (kstep < 9) ? kstep : kstep - 9;
    float v0 = W[(tap * 16 + k0) * 64 + n];
    float v1 = W[(tap * 16 + k0 + 1) * 64 + n];
    __half h0 = __float2half_rn(v0);
    __half h1 = __float2half_rn(v1);
    __half o0, o1;
    if (part == 0) { o0 = h0; o1 = h1; }
    else {
        o0 = __float2half_rn(v0 - __half2float(h0));
        o1 = __float2half_rn(v1 - __half2float(h1));
    }
    uint32_t w = (uint32_t)__half_as_ushort(o0) |
                 ((uint32_t)__half_as_ushort(o1) << 16);
    g_bfrag[idx] = w;
}

// ---------------- main step kernel ----------------
__global__ __launch_bounds__(256, 2)
void lstm_step_mma(const float* __restrict__ bias,
                   const __half* __restrict__ hh_in,
                   const __half* __restrict__ hl_in,
                   __half* __restrict__ hh_out,
                   __half* __restrict__ hl_out,
                   float* __restrict__ c_state,
                   int t)
{
    extern __shared__ char smem[];
    const uint32_t sb = smem_u32(smem);
    const int tid  = threadIdx.x;
    const int wid  = tid >> 5;
    const int lane = tid & 31;
    const int x0 = blockIdx.x * TLX;
    const int y0 = blockIdx.y * TLY;
    const int b  = blockIdx.z;

    // ---- stage strips (zero halo), XOR-swizzled 16B halves ----
    {
        const long xg = ((long)(b * TT + t)) * (HH * WW * CIN);
        const long hg = ((long)b) * (HH * WW * CIN);
        #pragma unroll 1
        for (int i = tid; i < 4 * 10 * 34; i += 256) {
            int comp = i / 340;
            int idx  = i - comp * 340;
            int row  = idx / 34;
            int col  = idx - row * 34;
            int y  = y0 + row - 1;
            int xc = x0 + col - 1;
            uint4 v0 = make_uint4(0, 0, 0, 0), v1 = v0;
            if ((unsigned)y < HH && (unsigned)xc < WW) {
                const __half* base =
                    (comp == 0) ? g_xhi : (comp == 1) ? g_xlo
                  : (comp == 2) ? hh_in : hl_in;
                long off = ((comp < 2) ? xg : hg) + (((long)y) * WW + xc) * CIN;
                const uint4* sp = (const uint4*)(base + off);
                v0 = sp[0];
                v1 = sp[1];
            }
            int pi = row * 34 + col;
            int sw = (pi & 4) << 2;   // 0 or 16
            char* dp = smem + comp * STRIP_BYTES + pi * 32;
            *(uint4*)(dp + (0  ^ sw)) = v0;
            *(uint4*)(dp + (16 ^ sw)) = v1;
        }
    }
    __syncthreads();

    // ---- per-warp GEMM: m32 pixels (one 32-px row) x n64 gates, K=288, 3 products ----
    const int prow = wid;                  // warp = image row within tile (0..7)
    const int g = lane >> 2;
    const int j = lane & 3;
    const int lcol  = lane & 15;           // ldmatrix pixel within m16 tile
    const int koff0 = lane & 16;           // ldmatrix k-half (bytes)

    float d[2][8][4];
    #pragma unroll
    for (int mt = 0; mt < 2; mt++)
        #pragma unroll
        for (int nt = 0; nt < 8; nt++)
            #pragma unroll
            for (int q = 0; q < 4; q++) d[mt][nt][q] = 0.f;

    #pragma unroll 1
    for (int tensor = 0; tensor < 2; tensor++) {
        const uint32_t shi = sb + tensor * 2 * STRIP_BYTES;
        #pragma unroll 1
        for (int tap = 0; tap < 9; tap++) {
            const int dy = tap / 3;
            const int dx = tap - dy * 3;
            const int pi0 = (prow + dy) * 34 + (dx + lcol);        // mtile 0
            const int pi1 = pi0 + 16;                              // mtile 1
            const uint32_t a0 =
                (uint32_t)(pi0 * 32 + (koff0 ^ ((pi0 & 4) << 2)));
            const uint32_t a1 =
                (uint32_t)(pi1 * 32 + (koff0 ^ ((pi1 & 4) << 2)));

            uint32_t ah0[4], ah1[4], al0[4], al1[4];
            ldsm_x4(ah0, shi + a0);
            ldsm_x4(ah1, shi + a1);
            ldsm_x4(al0, shi + STRIP_BYTES + a0);
            ldsm_x4(al1, shi + STRIP_BYTES + a1);

            const int kstep = tensor * 9 + tap;
            const char* bb = (const char*)g_bfrag + kstep * 4096 + lane * 8;
            #pragma unroll
            for (int nt = 0; nt < 8; nt++) {
                uint2 bh = __ldg((const uint2*)(bb + nt * 512));
                uint2 bl = __ldg((const uint2*)(bb + nt * 512 + 256));
                uint32_t bhr[2] = {bh.x, bh.y};
                uint32_t blr[2] = {bl.x, bl.y};
                mma16816(d[0][nt], ah0, bhr);
                mma16816(d[0][nt], ah0, blr);
                mma16816(d[0][nt], al0, bhr);
                mma16816(d[1][nt], ah1, bhr);
                mma16816(d[1][nt], ah1, blr);
                mma16816(d[1][nt], al1, bhr);
            }
        }
    }

    // ---- epilogue: LSTM update, fully register-local per lane ----
    const int ybase = y0 + prow;
    #pragma unroll
    for (int mt = 0; mt < 2; mt++) {
        #pragma unroll
        for (int ph = 0; ph < 2; ph++) {            // pixel g or g+8
            const int xc = x0 + mt * 16 + g + ph * 8;
            const long pb = (((long)b * HH + ybase) * WW + xc) * FF;
            const int co = ph * 2;                  // accumulator index base
            #pragma unroll
            for (int pr = 0; pr < 2; pr++) {        // channel pair A / B
                const int ch  = pr * 8 + 2 * j;     // channels ch, ch+1
                const int ntb = pr;                 // gate ntiles: ntb, +2, +4, +6
                float zi0 = d[mt][ntb][co]       + __ldg(bias + ch);
                float zi1 = d[mt][ntb][co + 1]   + __ldg(bias + ch + 1);
                float zf0 = d[mt][ntb + 2][co]   + __ldg(bias + 16 + ch);
                float zf1 = d[mt][ntb + 2][co+1] + __ldg(bias + 16 + ch + 1);
                float zc0 = d[mt][ntb + 4][co]   + __ldg(bias + 32 + ch);
                float zc1 = d[mt][ntb + 4][co+1] + __ldg(bias + 32 + ch + 1);
                float zo0 = d[mt][ntb + 6][co]   + __ldg(bias + 48 + ch);
                float zo1 = d[mt][ntb + 6][co+1] + __ldg(bias + 48 + ch + 1);

                float2 cp = *(const float2*)(c_state + pb + ch);
                float ig0 = 1.f / (1.f + __expf(-zi0));
                float ig1 = 1.f / (1.f + __expf(-zi1));
                float fg0 = 1.f / (1.f + __expf(-zf0));
                float fg1 = 1.f / (1.f + __expf(-zf1));
                float og0 = 1.f / (1.f + __expf(-zo0));
                float og1 = 1.f / (1.f + __expf(-zo1));
                float cn0 = fg0 * cp.x + ig0 * fmaxf(zc0, 0.f);
                float cn1 = fg1 * cp.y + ig1 * fmaxf(zc1, 0.f);
                float hn0 = og0 * fmaxf(cn0, 0.f);
                float hn1 = og1 * fmaxf(cn1, 0.f);

                *(float2*)(c_state + pb + ch) = make_float2(cn0, cn1);

                __half hh0 = __float2half_rn(hn0);
                __half hh1 = __float2half_rn(hn1);
                __half hl0 = __float2half_rn(hn0 - __half2float(hh0));
                __half hl1 = __float2half_rn(hn1 - __half2float(hh1));
                uint32_t whv = (uint32_t)__half_as_ushort(hh0) |
                               ((uint32_t)__half_as_ushort(hh1) << 16);
                uint32_t wlv = (uint32_t)__half_as_ushort(hl0) |
                               ((uint32_t)__half_as_ushort(hl1) << 16);
                *(uint32_t*)(hh_out + pb + ch) = whv;
                *(uint32_t*)(hl_out + pb + ch) = wlv;
            }
        }
    }
}

// ---------------- dense head ----------------
__global__ void dense_kernel(const __half* __restrict__ hh,
                             const __half* __restrict__ hl,
                             const float* __restrict__ dw,
                             const float* __restrict__ db,
                             float* __restrict__ out)
{
    int idx = blockIdx.x * blockDim.x + threadIdx.x;
    if (idx >= BB * HH * WW) return;
    const __half* hp = hh + (long)idx * FF;
    const __half* lp = hl + (long)idx * FF;
    float sum = 0.f;
    #pragma unroll
    for (int k = 0; k < FF; k++) {
        float h = __half2float(hp[k]) + __half2float(lp[k]);
        sum += h * __ldg(dw + k);
    }
    out[idx] = sum + __ldg(db);
}

extern "C" void kernel_launch(void* const* d_in, const int* in_sizes, int n_in,
                              void* d_out, int out_size)
{
    (void)in_sizes; (void)n_in; (void)out_size;
    const float* x    = (const float*)d_in[0];
    const float* wx   = (const float*)d_in[1];
    const float* wh   = (const float*)d_in[2];
    const float* bias = (const float*)d_in[3];
    const float* dw   = (const float*)d_in[4];
    const float* db   = (const float*)d_in[5];
    float* out = (float*)d_out;

    __half *hh, *hl;
    float* cbuf;
    cudaGetSymbolAddress((void**)&hh, g_hh);
    cudaGetSymbolAddress((void**)&hl, g_hl);
    cudaGetSymbolAddress((void**)&cbuf, g_c);

    convert_x_kernel<<<2048, 256>>>(x);
    zero_state_kernel<<<512, 256>>>();
    bfrag_kernel<<<(BFRAG_WORDS + 255) / 256, 256>>>(wx, wh);

    dim3 grid(WW / TLX, HH / TLY, BB);   // (3, 12, 16)
    for (int t = 0; t < TT; t++) {
        __half* hhi = hh + (t & 1) * STATE_ELEMS;
        __half* hli = hl + (t & 1) * STATE_ELEMS;
        __half* hho = hh + ((t + 1) & 1) * STATE_ELEMS;
        __half* hlo = hl + ((t + 1) & 1) * STATE_ELEMS;
        lstm_step_mma<<<grid, 256, SMEM_TOTAL>>>(
            bias, hhi, hli, hho, hlo, cbuf, t);
    }

    // t=23 -> final h in buffer index 0
    int npix = BB * HH * WW;
    dense_kernel<<<(npix + 255) / 256, 256>>>(hh, hl, dw, db, out);
}

// round 8
// speedup vs baseline: 6.2608x; 1.0146x over previous
#include <cuda_runtime.h>
#include <cuda_fp16.h>
#include <cstdint>
#include <math.h>

#define BB   16
#define TT   24
#define HH   96
#define WW   96
#define CIN  16
#define FF   16
#define GG   64

#define TLX  32
#define TLY  8
#define STATE_ELEMS (BB * HH * WW * FF)
#define XN (BB * TT * HH * WW * CIN)

// ---------------- device global scratch ----------------
__device__ __align__(16) __half g_xhi[XN];
__device__ __align__(16) __half g_xlo[XN];
__device__ __align__(16) __half g_hh[2][STATE_ELEMS];
__device__ __align__(16) __half g_hl[2][STATE_ELEMS];
__device__ __align__(16) float  g_c[STATE_ELEMS];
// B fragments: [kstep 18][ntile 8][lane 32][word 4] : word = {bh0,bh1,bl0,bl1}
#define BFRAG_WORDS (18 * 8 * 32 * 4)   // 18432 words (72KB, L1-resident)
__device__ __align__(16) uint32_t g_bfrag[BFRAG_WORDS];

// ---------------- smem layout (bytes) ----------------
// 4 strips: xhi, xlo, hhi, hlo ; each [row 10][col 34][ci 16] fp16
// XOR-swizzled: pixel pi stores its two 16B halves at pi*32 + (half ^ ((pi&4)<<2))
#define STRIP_BYTES (10 * 34 * CIN * 2)     // 10880
#define SMEM_TOTAL  (4 * STRIP_BYTES)       // 43520

// ---------------- mma / ldmatrix helpers ----------------
__device__ __forceinline__ void mma16816(float* d, const uint32_t* a,
                                         uint32_t b0, uint32_t b1) {
    asm volatile(
        "mma.sync.aligned.m16n8k16.row.col.f32.f16.f16.f32 "
        "{%0,%1,%2,%3}, {%4,%5,%6,%7}, {%8,%9}, {%0,%1,%2,%3};"
        : "+f"(d[0]), "+f"(d[1]), "+f"(d[2]), "+f"(d[3])
        : "r"(a[0]), "r"(a[1]), "r"(a[2]), "r"(a[3]), "r"(b0), "r"(b1));
}
__device__ __forceinline__ void ldsm_x4(uint32_t* a, uint32_t addr) {
    asm volatile(
        "ldmatrix.sync.aligned.m8n8.x4.shared.b16 {%0,%1,%2,%3}, [%4];"
        : "=r"(a[0]), "=r"(a[1]), "=r"(a[2]), "=r"(a[3]) : "r"(addr));
}
__device__ __forceinline__ uint32_t smem_u32(const void* p) {
    uint32_t a;
    asm("{ .reg .u64 t; cvta.to.shared.u64 t, %1; cvt.u32.u64 %0, t; }"
        : "=r"(a) : "l"(p));
    return a;
}

// ---------------- setup kernels ----------------
__global__ void convert_x_kernel(const float* __restrict__ x) {
    for (long i = blockIdx.x * (long)blockDim.x + threadIdx.x; i < XN;
         i += (long)gridDim.x * blockDim.x) {
        float v = x[i];
        __half hi = __float2half_rn(v);
        __half lo = __float2half_rn(v - __half2float(hi));
        g_xhi[i] = hi;
        g_xlo[i] = lo;
    }
}

__global__ void zero_state_kernel() {
    __half z = __float2half_rn(0.f);
    for (int i = blockIdx.x * blockDim.x + threadIdx.x; i < STATE_ELEMS;
         i += gridDim.x * blockDim.x) {
        g_hh[0][i] = z;
        g_hl[0][i] = z;
        g_c[i] = 0.f;
    }
}

__global__ void bfrag_kernel(const float* __restrict__ wx,
                             const float* __restrict__ wh) {
    int idx = blockIdx.x * blockDim.x + threadIdx.x;
    if (idx >= BFRAG_WORDS) return;
    int w     = idx & 3;           // 0:bh0 1:bh1 2:bl0 3:bl1
    int lane  = (idx >> 2) & 31;
    int nt    = (idx >> 7) & 7;
    int kstep = idx >> 10;
    int part = w >> 1;
    int reg  = w & 1;
    int j = lane & 3;
    int n = nt * 8 + (lane >> 2);
    int k0 = reg * 8 + 2 * j;
    const float* W = (kstep < 9) ? wx : wh;
    int tap = (kstep < 9) ? kstep : kstep - 9;
    float v0 = W[(tap * 16 + k0) * 64 + n];
    float v1 = W[(tap * 16 + k0 + 1) * 64 + n];
    __half h0 = __float2half_rn(v0);
    __half h1 = __float2half_rn(v1);
    __half o0, o1;
    if (part == 0) { o0 = h0; o1 = h1; }
    else {
        o0 = __float2half_rn(v0 - __half2float(h0));
        o1 = __float2half_rn(v1 - __half2float(h1));
    }
    uint32_t word = (uint32_t)__half_as_ushort(o0) |
                    ((uint32_t)__half_as_ushort(o1) << 16);
    g_bfrag[idx] = word;
}

// ---------------- main step kernel ----------------
__global__ __launch_bounds__(256, 2)
void lstm_step_mma(const float* __restrict__ bias,
                   const __half* __restrict__ hh_in,
                   const __half* __restrict__ hl_in,
                   __half* __restrict__ hh_out,
                   __half* __restrict__ hl_out,
                   float* __restrict__ c_state,
                   int t)
{
    extern __shared__ char smem[];
    const uint32_t sb = smem_u32(smem);
    const int tid  = threadIdx.x;
    const int wid  = tid >> 5;
    const int lane = tid & 31;
    const int x0 = blockIdx.x * TLX;
    const int y0 = blockIdx.y * TLY;
    const int b  = blockIdx.z;

    // ---- stage strips (zero halo), XOR-swizzled 16B halves ----
    {
        const long xg = ((long)(b * TT + t)) * (HH * WW * CIN);
        const long hg = ((long)b) * (HH * WW * CIN);
        #pragma unroll 1
        for (int i = tid; i < 4 * 10 * 34; i += 256) {
            int comp = i / 340;
            int idx  = i - comp * 340;
            int row  = idx / 34;
            int col  = idx - row * 34;
            int y  = y0 + row - 1;
            int xc = x0 + col - 1;
            uint4 v0 = make_uint4(0, 0, 0, 0), v1 = v0;
            if ((unsigned)y < HH && (unsigned)xc < WW) {
                const __half* base =
                    (comp == 0) ? g_xhi : (comp == 1) ? g_xlo
                  : (comp == 2) ? hh_in : hl_in;
                long off = ((comp < 2) ? xg : hg) + (((long)y) * WW + xc) * CIN;
                const uint4* sp = (const uint4*)(base + off);
                v0 = sp[0];
                v1 = sp[1];
            }
            int pi = row * 34 + col;
            int sw = (pi & 4) << 2;   // 0 or 16
            char* dp = smem + comp * STRIP_BYTES + pi * 32;
            *(uint4*)(dp + (0  ^ sw)) = v0;
            *(uint4*)(dp + (16 ^ sw)) = v1;
        }
    }
    __syncthreads();

    // ---- per-warp GEMM: m32 pixels (one 32-px row) x n64 gates, K=288, 3 products ----
    const int prow = wid;                  // warp = image row within tile (0..7)
    const int g = lane >> 2;
    const int j = lane & 3;
    const int lcol  = lane & 15;           // ldmatrix pixel within m16 tile
    const int koff0 = lane & 16;           // ldmatrix k-half (bytes)

    float d[2][8][4];
    #pragma unroll
    for (int mt = 0; mt < 2; mt++)
        #pragma unroll
        for (int nt = 0; nt < 8; nt++)
            #pragma unroll
            for (int q = 0; q < 4; q++) d[mt][nt][q] = 0.f;

    #pragma unroll 1
    for (int tensor = 0; tensor < 2; tensor++) {
        const uint32_t shi = sb + tensor * 2 * STRIP_BYTES;
        #pragma unroll 1
        for (int tap = 0; tap < 9; tap++) {
            const int dy = tap / 3;
            const int dx = tap - dy * 3;
            const int pi0 = (prow + dy) * 34 + (dx + lcol);        // mtile 0
            const int pi1 = pi0 + 16;                              // mtile 1
            const uint32_t a0 =
                (uint32_t)(pi0 * 32 + (koff0 ^ ((pi0 & 4) << 2)));
            const uint32_t a1 =
                (uint32_t)(pi1 * 32 + (koff0 ^ ((pi1 & 4) << 2)));

            uint32_t ah0[4], ah1[4], al0[4], al1[4];
            ldsm_x4(ah0, shi + a0);
            ldsm_x4(ah1, shi + a1);
            ldsm_x4(al0, shi + STRIP_BYTES + a0);
            ldsm_x4(al1, shi + STRIP_BYTES + a1);

            const int kstep = tensor * 9 + tap;
            const uint4* bb = (const uint4*)g_bfrag + (kstep * 8) * 32 + lane;
            // process n-tiles in pairs: 4 independent accumulators per pair,
            // every accumulator reused at distance 4 (breaks HMMA RAW chains)
            #pragma unroll
            for (int p = 0; p < 4; p++) {
                const int n0 = 2 * p;
                const int n1 = 2 * p + 1;
                uint4 b0 = __ldg(bb + n0 * 32);
                uint4 b1 = __ldg(bb + n1 * 32);
                mma16816(d[0][n0], ah0, b0.x, b0.y);
                mma16816(d[1][n0], ah1, b0.x, b0.y);
                mma16816(d[0][n1], ah0, b1.x, b1.y);
                mma16816(d[1][n1], ah1, b1.x, b1.y);
                mma16816(d[0][n0], ah0, b0.z, b0.w);
                mma16816(d[1][n0], ah1, b0.z, b0.w);
                mma16816(d[0][n1], ah0, b1.z, b1.w);
                mma16816(d[1][n1], ah1, b1.z, b1.w);
                mma16816(d[0][n0], al0, b0.x, b0.y);
                mma16816(d[1][n0], al1, b0.x, b0.y);
                mma16816(d[0][n1], al0, b1.x, b1.y);
                mma16816(d[1][n1], al1, b1.x, b1.y);
            }
        }
    }

    // ---- epilogue: LSTM update, fully register-local per lane ----
    const int ybase = y0 + prow;
    #pragma unroll
    for (int mt = 0; mt < 2; mt++) {
        #pragma unroll
        for (int ph = 0; ph < 2; ph++) {            // pixel g or g+8
            const int xc = x0 + mt * 16 + g + ph * 8;
            const long pb = (((long)b * HH + ybase) * WW + xc) * FF;
            const int co = ph * 2;                  // accumulator index base
            #pragma unroll
            for (int pr = 0; pr < 2; pr++) {        // channel pair A / B
                const int ch  = pr * 8 + 2 * j;     // channels ch, ch+1
                const int ntb = pr;                 // gate ntiles: ntb, +2, +4, +6
                float zi0 = d[mt][ntb][co]       + __ldg(bias + ch);
                float zi1 = d[mt][ntb][co + 1]   + __ldg(bias + ch + 1);
                float zf0 = d[mt][ntb + 2][co]   + __ldg(bias + 16 + ch);
                float zf1 = d[mt][ntb + 2][co+1] + __ldg(bias + 16 + ch + 1);
                float zc0 = d[mt][ntb + 4][co]   + __ldg(bias + 32 + ch);
                float zc1 = d[mt][ntb + 4][co+1] + __ldg(bias + 32 + ch + 1);
                float zo0 = d[mt][ntb + 6][co]   + __ldg(bias + 48 + ch);
                float zo1 = d[mt][ntb + 6][co+1] + __ldg(bias + 48 + ch + 1);

                float2 cp = *(const float2*)(c_state + pb + ch);
                float ig0 = 1.f / (1.f + __expf(-zi0));
                float ig1 = 1.f / (1.f + __expf(-zi1));
                float fg0 = 1.f / (1.f + __expf(-zf0));
                float fg1 = 1.f / (1.f + __expf(-zf1));
                float og0 = 1.f / (1.f + __expf(-zo0));
                float og1 = 1.f / (1.f + __expf(-zo1));
                float cn0 = fg0 * cp.x + ig0 * fmaxf(zc0, 0.f);
                float cn1 = fg1 * cp.y + ig1 * fmaxf(zc1, 0.f);
                float hn0 = og0 * fmaxf(cn0, 0.f);
                float hn1 = og1 * fmaxf(cn1, 0.f);

                *(float2*)(c_state + pb + ch) = make_float2(cn0, cn1);

                __half hh0 = __float2half_rn(hn0);
                __half hh1 = __float2half_rn(hn1);
                __half hl0 = __float2half_rn(hn0 - __half2float(hh0));
                __half hl1 = __float2half_rn(hn1 - __half2float(hh1));
                uint32_t whv = (uint32_t)__half_as_ushort(hh0) |
                               ((uint32_t)__half_as_ushort(hh1) << 16);
                uint32_t wlv = (uint32_t)__half_as_ushort(hl0) |
                               ((uint32_t)__half_as_ushort(hl1) << 16);
                *(uint32_t*)(hh_out + pb + ch) = whv;
                *(uint32_t*)(hl_out + pb + ch) = wlv;
            }
        }
    }
}

// ---------------- dense head ----------------
__global__ void dense_kernel(const __half* __restrict__ hh,
                             const __half* __restrict__ hl,
                             const float* __restrict__ dw,
                             const float* __restrict__ db,
                             float* __restrict__ out)
{
    int idx = blockIdx.x * blockDim.x + threadIdx.x;
    if (idx >= BB * HH * WW) return;
    const __half* hp = hh + (long)idx * FF;
    const __half* lp = hl + (long)idx * FF;
    float sum = 0.f;
    #pragma unroll
    for (int k = 0; k < FF; k++) {
        float h = __half2float(hp[k]) + __half2float(lp[k]);
        sum += h * __ldg(dw + k);
    }
    out[idx] = sum + __ldg(db);
}

extern "C" void kernel_launch(void* const* d_in, const int* in_sizes, int n_in,
                              void* d_out, int out_size)
{
    (void)in_sizes; (void)n_in; (void)out_size;
    const float* x    = (const float*)d_in[0];
    const float* wx   = (const float*)d_in[1];
    const float* wh   = (const float*)d_in[2];
    const float* bias = (const float*)d_in[3];
    const float* dw   = (const float*)d_in[4];
    const float* db   = (const float*)d_in[5];
    float* out = (float*)d_out;

    __half *hh, *hl;
    float* cbuf;
    cudaGetSymbolAddress((void**)&hh, g_hh);
    cudaGetSymbolAddress((void**)&hl, g_hl);
    cudaGetSymbolAddress((void**)&cbuf, g_c);

    convert_x_kernel<<<2048, 256>>>(x);
    zero_state_kernel<<<512, 256>>>();
    bfrag_kernel<<<(BFRAG_WORDS + 255) / 256, 256>>>(wx, wh);

    dim3 grid(WW / TLX, HH / TLY, BB);   // (3, 12, 16)
    for (int t = 0; t < TT; t++) {
        __half* hhi = hh + (t & 1) * STATE_ELEMS;
        __half* hli = hl + (t & 1) * STATE_ELEMS;
        __half* hho = hh + ((t + 1) & 1) * STATE_ELEMS;
        __half* hlo = hl + ((t + 1) & 1) * STATE_ELEMS;
        lstm_step_mma<<<grid, 256, SMEM_TOTAL>>>(
            bias, hhi, hli, hho, hlo, cbuf, t);
    }

    // t=23 -> final h in buffer index 0
    int npix = BB * HH * WW;
    dense_kernel<<<(npix + 255) / 256, 256>>>(hh, hl, dw, db, out);
}